// round 7
// baseline (speedup 1.0000x reference)
#include <cuda_runtime.h>
#include <cstdint>
#include <cstddef>

// ---------------------------------------------------------------------------
// MPConv fused GNN edge-MLP + scatter on GB300 (sm_103a)
// R7 = R6 + broadcast-weight GEMM1 remap (warp spans 64 edges, weights are
//      pure-broadcast raw f32x2 pairs), LN via smem partial exchange,
//      parallel dtype-detect.
// ---------------------------------------------------------------------------

#define NODES_MAX 100000
#define E_TILE    128
#define NTHREADS  256

typedef unsigned long long ull_t;

__device__ __align__(16) float g_AB[(size_t)NODES_MAX * 128];   // A||B per node
__device__ __align__(16) float g_G[(size_t)NODES_MAX * 64];     // scattered g sums
__device__ __align__(16) float g_degf[NODES_MAX];               // edge counts
__device__ int g_idx64;

__device__ __forceinline__ float gelu_exact(float v) {
    return 0.5f * v * (1.0f + erff(v * 0.70710678118654752440f));
}

__device__ __forceinline__ void fma2(ull_t& d, ull_t a, ull_t b) {
    asm("fma.rn.f32x2 %0, %1, %2, %0;" : "+l"(d) : "l"(a), "l"(b));
}
#define UNPK(lo, hi, v) asm("mov.b64 {%0,%1}, %2;" : "=f"(lo), "=f"(hi) : "l"(v))
#define DUP(d, f)       asm("mov.b64 %0, {%1, %1};" : "=l"(d) : "f"(f))

// ---------------------------------------------------------------------------
__global__ void zero_scratch_kernel(int nG4, int nD4) {
    int idx = blockIdx.x * blockDim.x + threadIdx.x;
    if (idx < nG4)            ((float4*)g_G)[idx]          = make_float4(0.f, 0.f, 0.f, 0.f);
    else if (idx < nG4 + nD4) ((float4*)g_degf)[idx - nG4] = make_float4(0.f, 0.f, 0.f, 0.f);
}

// parallel dtype detect: int32 data misread as int64 escapes [0,N) w.h.p.
__global__ void detect_idx_kernel(const void* edge_index, int N) {
    __shared__ int s_bad;
    int t = threadIdx.x;
    if (t == 0) s_bad = 0;
    __syncthreads();
    long long v = ((const long long*)edge_index)[t];
    if (v < 0 || v >= (long long)N) atomicOr(&s_bad, 1);
    __syncthreads();
    if (t == 0) g_idx64 = !s_bad;
}

__device__ __forceinline__ int load_edge_idx(const void* ei, long long pos, int idx64) {
    if (idx64) return (int)((const long long*)ei)[pos];
    return ((const int*)ei)[pos];
}

// ---------------------------------------------------------------------------
#define FMA_ROW(ACC, A, B)                          \
    ACC.x = fmaf((A), (B).x, ACC.x);                \
    ACC.y = fmaf((A), (B).y, ACC.y);                \
    ACC.z = fmaf((A), (B).z, ACC.z);                \
    ACC.w = fmaf((A), (B).w, ACC.w);

// Precompute g_AB. 64 nodes x 128 ch per CTA, xT stride 65 (conflict-free).
__global__ void __launch_bounds__(NTHREADS, 2)
precompute_kernel(const float* __restrict__ x,
                  const float* __restrict__ W1,
                  const float* __restrict__ b1,
                  int N) {
    extern __shared__ float sm[];
    float* xT = sm;                  // [k][node], stride 65
    float* Wc = sm + 64 * 65 + 4;    // [k][c] 64x128

    int t = threadIdx.x;
    int n_base = blockIdx.x * 64;

#pragma unroll
    for (int it = 0; it < 32; ++it) {
        int idx = t + it * NTHREADS;
        int k = idx >> 7, c = idx & 127;
        Wc[idx] = (c < 64) ? W1[k * 64 + c] : W1[(64 + k) * 64 + (c - 64)];
    }
#pragma unroll
    for (int it = 0; it < 16; ++it) {
        int idx = t + it * NTHREADS;
        int node = idx >> 6, k = idx & 63;
        int gn = n_base + node;
        xT[k * 65 + node] = (gn < N) ? x[(size_t)gn * 64 + k] : 0.f;
    }
    __syncthreads();

    int tx = t & 31, ty = t >> 5;
    int c0 = tx * 4, n0 = ty * 8;

    float4 acc[8];
#pragma unroll
    for (int r = 0; r < 8; ++r) acc[r] = make_float4(0.f, 0.f, 0.f, 0.f);

#pragma unroll 8
    for (int k = 0; k < 64; ++k) {
        float4 b = *(const float4*)&Wc[k * 128 + c0];
        const float* xp = &xT[k * 65 + n0];
#pragma unroll
        for (int r = 0; r < 8; ++r) { FMA_ROW(acc[r], xp[r], b); }
    }

    float4 badd = make_float4(0.f, 0.f, 0.f, 0.f);
    if (c0 < 64) badd = *(const float4*)&b1[c0];

#pragma unroll
    for (int r = 0; r < 8; ++r) {
        int gn = n_base + n0 + r;
        if (gn < N) {
            float4 v = acc[r];
            v.x += badd.x; v.y += badd.y; v.z += badd.z; v.w += badd.w;
            *(float4*)&g_AB[(size_t)gn * 128 + c0] = v;
        }
    }
}

// ---------------------------------------------------------------------------
// Edge kernel. 128 edges/block, 256 threads.
// Thread t: pr = t&63 -> edges (2pr, 2pr+1);  cg = t>>6 -> channels [cg*16,+16)
// Each warp: 32 consecutive pairs, ONE channel group -> weight LDS broadcast.
// dyn smem (30208 B):
//   iidx[128] @0, jidx[128] @512
//   W1p [32][64] f32 raw  @1024   (8192)
//   eaT [32][132] f32     @9216   (16896)
//   sPart[4][128] f32     @26112  (2048)
//   qPart[4][128] f32     @28160  (2048)
__global__ void __launch_bounds__(NTHREADS, 3)
edge_kernel(const void* __restrict__ edge_index,
            const float* __restrict__ edge_attr,
            const float* __restrict__ W1,
            const float* __restrict__ gamma,
            const float* __restrict__ beta,
            int E) {
    extern __shared__ char smraw[];
    int*   iidx  = (int*)smraw;
    int*   jidx  = iidx + 128;
    float* W1p   = (float*)(smraw + 1024);
    float* eaT   = (float*)(smraw + 9216);
    float* sPart = (float*)(smraw + 26112);
    float* qPart = (float*)(smraw + 28160);

    int t = threadIdx.x;
    long long e_base = (long long)blockIdx.x * E_TILE;
    int idx64 = g_idx64;

    if (t < 128) iidx[t] = load_edge_idx(edge_index, e_base + t, idx64);
    else         jidx[t - 128] = load_edge_idx(edge_index, (long long)E + e_base + (t - 128), idx64);

    // W1p: raw copy of W1 rows 128..159 (2048 floats = 512 float4)
    {
        const float4* src = (const float4*)(W1 + 128 * 64);
        float4* dst = (float4*)W1p;
        dst[t]       = src[t];
        dst[t + 256] = src[t + 256];
    }
    // edge_attr transposed: eaT[k][e], stride 132
    {
        const float4* ea4 = (const float4*)edge_attr;
#pragma unroll
        for (int it = 0; it < 4; ++it) {
            int slot = t + it * NTHREADS;           // 0..1023
            int e = slot >> 3, q = slot & 7;
            float4 v = ea4[e_base * 8 + slot];
            int k = q * 4;
            eaT[(k + 0) * 132 + e] = v.x;
            eaT[(k + 1) * 132 + e] = v.y;
            eaT[(k + 2) * 132 + e] = v.z;
            eaT[(k + 3) * 132 + e] = v.w;
        }
    }
    __syncthreads();

    int pr = t & 63;      // edge pair
    int cg = t >> 6;      // channel group
    int e0 = 2 * pr, e1 = 2 * pr + 1;

    // acc[cp][e]: channel-pair cp (0..7) packed as f32x2, edge e (0..1)
    ull_t acc[8][2];
#pragma unroll
    for (int i = 0; i < 8; ++i) { acc[i][0] = 0ull; acc[i][1] = 0ull; }

    const ull_t* Wb = (const ull_t*)W1p;    // 32 ull per k-row

    // -------- GEMM1: h = ea @ W1c (weights broadcast, A duplicated) --------
#pragma unroll 4
    for (int kk = 0; kk < 32; ++kk) {
        float2 a = *(const float2*)&eaT[kk * 132 + e0];
        ull_t A0, A1;
        DUP(A0, a.x);
        DUP(A1, a.y);
        const ull_t* wp = Wb + kk * 32 + cg * 8;
        ulonglong2 w0 = *(const ulonglong2*)(wp);
        ulonglong2 w1 = *(const ulonglong2*)(wp + 2);
        ulonglong2 w2 = *(const ulonglong2*)(wp + 4);
        ulonglong2 w3 = *(const ulonglong2*)(wp + 6);
        fma2(acc[0][0], A0, w0.x); fma2(acc[0][1], A1, w0.x);
        fma2(acc[1][0], A0, w0.y); fma2(acc[1][1], A1, w0.y);
        fma2(acc[2][0], A0, w1.x); fma2(acc[2][1], A1, w1.x);
        fma2(acc[3][0], A0, w1.y); fma2(acc[3][1], A1, w1.y);
        fma2(acc[4][0], A0, w2.x); fma2(acc[4][1], A1, w2.x);
        fma2(acc[5][0], A0, w2.y); fma2(acc[5][1], A1, w2.y);
        fma2(acc[6][0], A0, w3.x); fma2(acc[6][1], A1, w3.x);
        fma2(acc[7][0], A0, w3.y); fma2(acc[7][1], A1, w3.y);
    }

    // unpack: v0 = edge e0's 16 channels, v1 = edge e1's
    float v0[16], v1[16];
#pragma unroll
    for (int cp = 0; cp < 8; ++cp) {
        UNPK(v0[cp * 2], v0[cp * 2 + 1], acc[cp][0]);
        UNPK(v1[cp * 2], v1[cp * 2 + 1], acc[cp][1]);
    }

    // -------- gather precomputed node parts --------
    const float4* AB4 = (const float4*)g_AB;
    int vi0 = iidx[e0], vj0 = jidx[e0];
    int vi1 = iidx[e1], vj1 = jidx[e1];
#pragma unroll
    for (int q = 0; q < 4; ++q) {
        float4 a0 = AB4[(size_t)vi0 * 32 + cg * 4 + q];
        float4 b0 = AB4[(size_t)vj0 * 32 + 16 + cg * 4 + q];
        v0[q * 4 + 0] += a0.x + b0.x; v0[q * 4 + 1] += a0.y + b0.y;
        v0[q * 4 + 2] += a0.z + b0.z; v0[q * 4 + 3] += a0.w + b0.w;
        float4 a1 = AB4[(size_t)vi1 * 32 + cg * 4 + q];
        float4 b1 = AB4[(size_t)vj1 * 32 + 16 + cg * 4 + q];
        v1[q * 4 + 0] += a1.x + b1.x; v1[q * 4 + 1] += a1.y + b1.y;
        v1[q * 4 + 2] += a1.z + b1.z; v1[q * 4 + 3] += a1.w + b1.w;
    }

    // -------- LN partial sums, exchanged across the 4 cg-threads via smem ---
    float s0 = 0.f, q0 = 0.f, s1 = 0.f, q1 = 0.f;
#pragma unroll
    for (int c = 0; c < 16; ++c) {
        s0 += v0[c]; q0 = fmaf(v0[c], v0[c], q0);
        s1 += v1[c]; q1 = fmaf(v1[c], v1[c], q1);
    }
    *(float2*)&sPart[cg * 128 + e0] = make_float2(s0, s1);
    *(float2*)&qPart[cg * 128 + e0] = make_float2(q0, q1);
    __syncthreads();

    float ss0 = 0.f, ss1 = 0.f, qq0 = 0.f, qq1 = 0.f;
#pragma unroll
    for (int g = 0; g < 4; ++g) {
        float2 sv = *(const float2*)&sPart[g * 128 + e0];
        float2 qv = *(const float2*)&qPart[g * 128 + e0];
        ss0 += sv.x; ss1 += sv.y;
        qq0 += qv.x; qq1 += qv.y;
    }
    float mu0 = ss0 * (1.0f / 64.0f);
    float mu1 = ss1 * (1.0f / 64.0f);
    float r0  = rsqrtf(qq0 * (1.0f / 64.0f) - mu0 * mu0 + 1e-5f);
    float r1  = rsqrtf(qq1 * (1.0f / 64.0f) - mu1 * mu1 + 1e-5f);

    // -------- gamma/beta + GELU --------
    const float4* gp = (const float4*)(gamma + cg * 16);
    const float4* bp = (const float4*)(beta + cg * 16);
#pragma unroll
    for (int q = 0; q < 4; ++q) {
        float4 gv = gp[q];
        float4 bv = bp[q];
        float gmr[4] = {gv.x, gv.y, gv.z, gv.w};
        float btr[4] = {bv.x, bv.y, bv.z, bv.w};
#pragma unroll
        for (int c = 0; c < 4; ++c) {
            int ci = q * 4 + c;
            v0[ci] = gelu_exact((v0[ci] - mu0) * r0 * gmr[c] + btr[c]);
            v1[ci] = gelu_exact((v1[ci] - mu1) * r1 * gmr[c] + btr[c]);
        }
    }

    // -------- scatter g onto G[j]; degree from cg==0 --------
    {
        float* p0 = g_G + (size_t)vj0 * 64 + cg * 16;
#pragma unroll
        for (int q = 0; q < 4; ++q)
            asm volatile("red.global.add.v4.f32 [%0], {%1,%2,%3,%4};"
                         :: "l"(p0 + q * 4), "f"(v0[q * 4 + 0]), "f"(v0[q * 4 + 1]),
                            "f"(v0[q * 4 + 2]), "f"(v0[q * 4 + 3]) : "memory");
        float* p1 = g_G + (size_t)vj1 * 64 + cg * 16;
#pragma unroll
        for (int q = 0; q < 4; ++q)
            asm volatile("red.global.add.v4.f32 [%0], {%1,%2,%3,%4};"
                         :: "l"(p1 + q * 4), "f"(v1[q * 4 + 0]), "f"(v1[q * 4 + 1]),
                            "f"(v1[q * 4 + 2]), "f"(v1[q * 4 + 3]) : "memory");
        if (cg == 0) {
            asm volatile("red.global.add.f32 [%0], %1;"
                         :: "l"(g_degf + vj0), "f"(1.0f) : "memory");
            asm volatile("red.global.add.f32 [%0], %1;"
                         :: "l"(g_degf + vj1), "f"(1.0f) : "memory");
        }
    }
}

// ---------------------------------------------------------------------------
// Node kernel: out[n] = G[n] @ W2 + deg[n] * b2. 64 nodes per CTA.
__global__ void __launch_bounds__(NTHREADS, 2)
node_kernel(const float* __restrict__ W2,
            const float* __restrict__ b2,
            float* __restrict__ out,
            int N) {
    extern __shared__ float sm[];
    float* GT  = sm;                  // [k][node], stride 65
    float* W2s = sm + 64 * 65 + 4;    // [k][c] 64x64

    int t = threadIdx.x;
    int n_base = blockIdx.x * 64;

#pragma unroll
    for (int it = 0; it < 16; ++it) {
        int idx = t + it * NTHREADS;
        int node = idx >> 6, k = idx & 63;
        int gn = n_base + node;
        GT[k * 65 + node] = (gn < N) ? g_G[(size_t)gn * 64 + k] : 0.f;
        W2s[idx] = W2[idx];
    }
    __syncthreads();

    int tx = t & 15, ty = t >> 4;
    int c0 = tx * 4, n0 = ty * 4;

    float4 acc[4];
#pragma unroll
    for (int r = 0; r < 4; ++r) acc[r] = make_float4(0.f, 0.f, 0.f, 0.f);

#pragma unroll 8
    for (int k = 0; k < 64; ++k) {
        float4 b = *(const float4*)&W2s[k * 64 + c0];
        const float* gpv = &GT[k * 65 + n0];
#pragma unroll
        for (int r = 0; r < 4; ++r) { FMA_ROW(acc[r], gpv[r], b); }
    }

    float4 b2v = *(const float4*)&b2[c0];
#pragma unroll
    for (int r = 0; r < 4; ++r) {
        int gn = n_base + n0 + r;
        if (gn < N) {
            float d = g_degf[gn];
            float4 v = acc[r];
            v.x = fmaf(d, b2v.x, v.x); v.y = fmaf(d, b2v.y, v.y);
            v.z = fmaf(d, b2v.z, v.z); v.w = fmaf(d, b2v.w, v.w);
            *(float4*)&out[(size_t)gn * 64 + c0] = v;
        }
    }
}

// ---------------------------------------------------------------------------
extern "C" void kernel_launch(void* const* d_in, const int* in_sizes, int n_in,
                              void* d_out, int out_size) {
    const float* x          = (const float*)d_in[0];
    const void*  edge_index = d_in[1];
    const float* edge_attr  = (const float*)d_in[2];
    const float* W1         = (const float*)d_in[3];
    const float* b1         = (const float*)d_in[4];
    const float* gamma      = (const float*)d_in[5];
    const float* beta       = (const float*)d_in[6];
    const float* W2         = (const float*)d_in[7];
    const float* b2         = (const float*)d_in[8];
    float*       out        = (float*)d_out;

    int N = in_sizes[0] / 64;     // 100000
    int E = in_sizes[2] / 32;     // 1600000

    const int SM_PRE  = (64 * 65 + 4 + 64 * 128) * 4;
    const int SM_EDGE = 30208;
    const int SM_NODE = (64 * 65 + 4 + 64 * 64) * 4;
    cudaFuncSetAttribute(precompute_kernel, cudaFuncAttributeMaxDynamicSharedMemorySize, SM_PRE);
    cudaFuncSetAttribute(edge_kernel,       cudaFuncAttributeMaxDynamicSharedMemorySize, SM_EDGE);
    cudaFuncSetAttribute(node_kernel,       cudaFuncAttributeMaxDynamicSharedMemorySize, SM_NODE);

    int nG4 = N * 16;
    int nD4 = (N + 3) / 4;
    int nz  = nG4 + nD4;

    detect_idx_kernel<<<1, 128>>>(edge_index, N);
    zero_scratch_kernel<<<(nz + 255) / 256, 256>>>(nG4, nD4);
    precompute_kernel<<<(N + 63) / 64, NTHREADS, SM_PRE>>>(x, W1, b1, N);
    edge_kernel<<<E / E_TILE, NTHREADS, SM_EDGE>>>(edge_index, edge_attr, W1,
                                                   gamma, beta, E);
    node_kernel<<<(N + 63) / 64, NTHREADS, SM_NODE>>>(W2, b2, out, N);
}

// round 8
// speedup vs baseline: 1.6466x; 1.6466x over previous
#include <cuda_runtime.h>
#include <cstdint>
#include <cstddef>

// ---------------------------------------------------------------------------
// MPConv fused GNN edge-MLP + scatter on GB300 (sm_103a)
// R8 = R6 (proven mapping: channel-lanes span one edge -> coalesced
//      gather/scatter) + raw-weight GEMM1 (dup via regs, -33% GEMM1 smem wf)
//      + scratch zeroing folded into precompute.
// ---------------------------------------------------------------------------

#define NODES_MAX 100000
#define E_TILE    128
#define NTHREADS  256

typedef unsigned long long ull_t;

__device__ __align__(16) float g_AB[(size_t)NODES_MAX * 128];   // A||B per node
__device__ __align__(16) float g_G[(size_t)NODES_MAX * 64];     // scattered g sums
__device__ __align__(16) float g_degf[NODES_MAX];               // edge counts
__device__ int g_idx64;

__device__ __forceinline__ float gelu_exact(float v) {
    return 0.5f * v * (1.0f + erff(v * 0.70710678118654752440f));
}

__device__ __forceinline__ void fma2(ull_t& d, ull_t a, ull_t b) {
    asm("fma.rn.f32x2 %0, %1, %2, %0;" : "+l"(d) : "l"(a), "l"(b));
}
#define UNPK(lo, hi, v) asm("mov.b64 {%0,%1}, %2;" : "=f"(lo), "=f"(hi) : "l"(v))
#define DUP(d, f)       asm("mov.b64 %0, {%1, %1};" : "=l"(d) : "f"(f))

// ---------------------------------------------------------------------------
// parallel dtype detect: int32 data misread as int64 escapes [0,N) w.h.p.
__global__ void detect_idx_kernel(const void* edge_index, int N) {
    __shared__ int s_bad;
    int t = threadIdx.x;
    if (t == 0) s_bad = 0;
    __syncthreads();
    long long v = ((const long long*)edge_index)[t];
    if (v < 0 || v >= (long long)N) atomicOr(&s_bad, 1);
    __syncthreads();
    if (t == 0) g_idx64 = !s_bad;
}

__device__ __forceinline__ int load_edge_idx(const void* ei, long long pos, int idx64) {
    if (idx64) return (int)((const long long*)ei)[pos];
    return ((const int*)ei)[pos];
}

// ---------------------------------------------------------------------------
#define FMA_ROW(ACC, A, B)                          \
    ACC.x = fmaf((A), (B).x, ACC.x);                \
    ACC.y = fmaf((A), (B).y, ACC.y);                \
    ACC.z = fmaf((A), (B).z, ACC.z);                \
    ACC.w = fmaf((A), (B).w, ACC.w);

// Precompute g_AB + zero this block's slice of g_G / g_degf.
// 64 nodes x 128 ch per CTA, xT stride 65 (conflict-free).
__global__ void __launch_bounds__(NTHREADS, 2)
precompute_kernel(const float* __restrict__ x,
                  const float* __restrict__ W1,
                  const float* __restrict__ b1,
                  int N) {
    extern __shared__ float sm[];
    float* xT = sm;                  // [k][node], stride 65
    float* Wc = sm + 64 * 65 + 4;    // [k][c] 64x128

    int t = threadIdx.x;
    int n_base = blockIdx.x * 64;

    // zero scratch for this block's nodes (independent of main work)
    {
        float4 z4 = make_float4(0.f, 0.f, 0.f, 0.f);
#pragma unroll
        for (int it = 0; it < 4; ++it) {
            int idx = t + it * NTHREADS;        // 0..1023 float4 slots
            int node = idx >> 4, q = idx & 15;
            int gn = n_base + node;
            if (gn < N) ((float4*)g_G)[(size_t)gn * 16 + q] = z4;
        }
        if (t < 64 && n_base + t < N) g_degf[n_base + t] = 0.f;
    }

#pragma unroll
    for (int it = 0; it < 32; ++it) {
        int idx = t + it * NTHREADS;
        int k = idx >> 7, c = idx & 127;
        Wc[idx] = (c < 64) ? W1[k * 64 + c] : W1[(64 + k) * 64 + (c - 64)];
    }
#pragma unroll
    for (int it = 0; it < 16; ++it) {
        int idx = t + it * NTHREADS;
        int node = idx >> 6, k = idx & 63;
        int gn = n_base + node;
        xT[k * 65 + node] = (gn < N) ? x[(size_t)gn * 64 + k] : 0.f;
    }
    __syncthreads();

    int tx = t & 31, ty = t >> 5;
    int c0 = tx * 4, n0 = ty * 8;

    float4 acc[8];
#pragma unroll
    for (int r = 0; r < 8; ++r) acc[r] = make_float4(0.f, 0.f, 0.f, 0.f);

#pragma unroll 8
    for (int k = 0; k < 64; ++k) {
        float4 b = *(const float4*)&Wc[k * 128 + c0];
        const float* xp = &xT[k * 65 + n0];
#pragma unroll
        for (int r = 0; r < 8; ++r) { FMA_ROW(acc[r], xp[r], b); }
    }

    float4 badd = make_float4(0.f, 0.f, 0.f, 0.f);
    if (c0 < 64) badd = *(const float4*)&b1[c0];

#pragma unroll
    for (int r = 0; r < 8; ++r) {
        int gn = n_base + n0 + r;
        if (gn < N) {
            float4 v = acc[r];
            v.x += badd.x; v.y += badd.y; v.z += badd.z; v.w += badd.w;
            *(float4*)&g_AB[(size_t)gn * 128 + c0] = v;
        }
    }
}

// ---------------------------------------------------------------------------
// Edge kernel. 128 edges/block, 256 threads, 4ch x 8edge per thread (R6 map).
// dyn smem (26112 B):
//   iidx[128] @0, jidx[128] @512
//   W1p [32][64] f32 raw @1024   (8192)
//   eaT [32][132] f32    @9216   (16896)
__global__ void __launch_bounds__(NTHREADS, 3)
edge_kernel(const void* __restrict__ edge_index,
            const float* __restrict__ edge_attr,
            const float* __restrict__ W1,
            const float* __restrict__ gamma,
            const float* __restrict__ beta,
            int E) {
    extern __shared__ char smraw[];
    int*   iidx = (int*)smraw;
    int*   jidx = iidx + 128;
    float* W1p  = (float*)(smraw + 1024);
    float* eaT  = (float*)(smraw + 9216);

    int t = threadIdx.x;
    long long e_base = (long long)blockIdx.x * E_TILE;
    int idx64 = g_idx64;

    if (t < 128) iidx[t] = load_edge_idx(edge_index, e_base + t, idx64);
    else         jidx[t - 128] = load_edge_idx(edge_index, (long long)E + e_base + (t - 128), idx64);

    // W1p: raw copy of W1 rows 128..159 (2048 floats = 512 float4)
    {
        const float4* src = (const float4*)(W1 + 128 * 64);
        float4* dst = (float4*)W1p;
        dst[t]       = src[t];
        dst[t + 256] = src[t + 256];
    }
    // edge_attr transposed: eaT[k][e], stride 132
    {
        const float4* ea4 = (const float4*)edge_attr;
#pragma unroll
        for (int it = 0; it < 4; ++it) {
            int slot = t + it * NTHREADS;           // 0..1023
            int e = slot >> 3, q = slot & 7;
            float4 v = ea4[e_base * 8 + slot];
            int k = q * 4;
            eaT[(k + 0) * 132 + e] = v.x;
            eaT[(k + 1) * 132 + e] = v.y;
            eaT[(k + 2) * 132 + e] = v.z;
            eaT[(k + 3) * 132 + e] = v.w;
        }
    }
    __syncthreads();

    int tx = t & 15, ty = t >> 4;
    int c0 = tx * 4, e0 = ty * 8;

    // acc[c*4+p]: channel c (0..3), edge-pair p (0..3), lanes = (e0+2p, e0+2p+1)
    ull_t acc[16];
#pragma unroll
    for (int i = 0; i < 16; ++i) acc[i] = 0ull;

    // -------- GEMM1: h = ea @ W1c --------
    // raw weight LDS.128 (16B/thread, 2 wf/warp) + in-reg duplication
#pragma unroll 4
    for (int kk = 0; kk < 32; ++kk) {
        float4 w = *(const float4*)&W1p[kk * 64 + c0];
        ull_t W0, W1r, W2r, W3r;
        DUP(W0, w.x); DUP(W1r, w.y); DUP(W2r, w.z); DUP(W3r, w.w);
        const float* ap = eaT + kk * 132 + e0;
        ulonglong2 A01 = *(const ulonglong2*)(ap);
        ulonglong2 A23 = *(const ulonglong2*)(ap + 4);
        fma2(acc[ 0], A01.x, W0);  fma2(acc[ 1], A01.y, W0);
        fma2(acc[ 2], A23.x, W0);  fma2(acc[ 3], A23.y, W0);
        fma2(acc[ 4], A01.x, W1r); fma2(acc[ 5], A01.y, W1r);
        fma2(acc[ 6], A23.x, W1r); fma2(acc[ 7], A23.y, W1r);
        fma2(acc[ 8], A01.x, W2r); fma2(acc[ 9], A01.y, W2r);
        fma2(acc[10], A23.x, W2r); fma2(acc[11], A23.y, W2r);
        fma2(acc[12], A01.x, W3r); fma2(acc[13], A01.y, W3r);
        fma2(acc[14], A23.x, W3r); fma2(acc[15], A23.y, W3r);
    }

    // -------- epilogue, pair-by-pair (register diet, R6-proven) --------
    float4 gmv = *(const float4*)&gamma[c0];
    float4 btv = *(const float4*)&beta[c0];
    const float4* AB4 = (const float4*)g_AB;

#pragma unroll
    for (int p = 0; p < 4; ++p) {
        int ea = e0 + 2 * p, eb = ea + 1;

        float va0, vb0, va1, vb1, va2, vb2, va3, vb3;
        UNPK(va0, vb0, acc[0 * 4 + p]);
        UNPK(va1, vb1, acc[1 * 4 + p]);
        UNPK(va2, vb2, acc[2 * 4 + p]);
        UNPK(va3, vb3, acc[3 * 4 + p]);

        {
            float4 Aa = AB4[(size_t)iidx[ea] * 32 + tx];
            float4 Ba = AB4[(size_t)jidx[ea] * 32 + 16 + tx];
            va0 += Aa.x + Ba.x; va1 += Aa.y + Ba.y;
            va2 += Aa.z + Ba.z; va3 += Aa.w + Ba.w;
        }
        {
            float4 Ab = AB4[(size_t)iidx[eb] * 32 + tx];
            float4 Bb = AB4[(size_t)jidx[eb] * 32 + 16 + tx];
            vb0 += Ab.x + Bb.x; vb1 += Ab.y + Bb.y;
            vb2 += Ab.z + Bb.z; vb3 += Ab.w + Bb.w;
        }

        float sa = va0 + va1 + va2 + va3;
        float sb = vb0 + vb1 + vb2 + vb3;
        float qa = fmaf(va0, va0, fmaf(va1, va1, fmaf(va2, va2, va3 * va3)));
        float qb = fmaf(vb0, vb0, fmaf(vb1, vb1, fmaf(vb2, vb2, vb3 * vb3)));
#pragma unroll
        for (int off = 8; off >= 1; off >>= 1) {
            sa += __shfl_xor_sync(0xffffffffu, sa, off, 16);
            sb += __shfl_xor_sync(0xffffffffu, sb, off, 16);
            qa += __shfl_xor_sync(0xffffffffu, qa, off, 16);
            qb += __shfl_xor_sync(0xffffffffu, qb, off, 16);
        }
        float mua = sa * (1.0f / 64.0f);
        float mub = sb * (1.0f / 64.0f);
        float ra  = rsqrtf(qa * (1.0f / 64.0f) - mua * mua + 1e-5f);
        float rb  = rsqrtf(qb * (1.0f / 64.0f) - mub * mub + 1e-5f);

        va0 = gelu_exact((va0 - mua) * ra * gmv.x + btv.x);
        va1 = gelu_exact((va1 - mua) * ra * gmv.y + btv.y);
        va2 = gelu_exact((va2 - mua) * ra * gmv.z + btv.z);
        va3 = gelu_exact((va3 - mua) * ra * gmv.w + btv.w);
        vb0 = gelu_exact((vb0 - mub) * rb * gmv.x + btv.x);
        vb1 = gelu_exact((vb1 - mub) * rb * gmv.y + btv.y);
        vb2 = gelu_exact((vb2 - mub) * rb * gmv.z + btv.z);
        vb3 = gelu_exact((vb3 - mub) * rb * gmv.w + btv.w);

        {
            int vja = jidx[ea];
            float* pa = g_G + (size_t)vja * 64 + c0;
            asm volatile("red.global.add.v4.f32 [%0], {%1,%2,%3,%4};"
                         :: "l"(pa), "f"(va0), "f"(va1), "f"(va2), "f"(va3) : "memory");
            int vjb = jidx[eb];
            float* pb = g_G + (size_t)vjb * 64 + c0;
            asm volatile("red.global.add.v4.f32 [%0], {%1,%2,%3,%4};"
                         :: "l"(pb), "f"(vb0), "f"(vb1), "f"(vb2), "f"(vb3) : "memory");
            if (tx == 0) {
                asm volatile("red.global.add.f32 [%0], %1;"
                             :: "l"(g_degf + vja), "f"(1.0f) : "memory");
                asm volatile("red.global.add.f32 [%0], %1;"
                             :: "l"(g_degf + vjb), "f"(1.0f) : "memory");
            }
        }
    }
}

// ---------------------------------------------------------------------------
// Node kernel: out[n] = G[n] @ W2 + deg[n] * b2. 64 nodes per CTA.
__global__ void __launch_bounds__(NTHREADS, 2)
node_kernel(const float* __restrict__ W2,
            const float* __restrict__ b2,
            float* __restrict__ out,
            int N) {
    extern __shared__ float sm[];
    float* GT  = sm;                  // [k][node], stride 65
    float* W2s = sm + 64 * 65 + 4;    // [k][c] 64x64

    int t = threadIdx.x;
    int n_base = blockIdx.x * 64;

#pragma unroll
    for (int it = 0; it < 16; ++it) {
        int idx = t + it * NTHREADS;
        int node = idx >> 6, k = idx & 63;
        int gn = n_base + node;
        GT[k * 65 + node] = (gn < N) ? g_G[(size_t)gn * 64 + k] : 0.f;
        W2s[idx] = W2[idx];
    }
    __syncthreads();

    int tx = t & 15, ty = t >> 4;
    int c0 = tx * 4, n0 = ty * 4;

    float4 acc[4];
#pragma unroll
    for (int r = 0; r < 4; ++r) acc[r] = make_float4(0.f, 0.f, 0.f, 0.f);

#pragma unroll 8
    for (int k = 0; k < 64; ++k) {
        float4 b = *(const float4*)&W2s[k * 64 + c0];
        const float* gpv = &GT[k * 65 + n0];
#pragma unroll
        for (int r = 0; r < 4; ++r) { FMA_ROW(acc[r], gpv[r], b); }
    }

    float4 b2v = *(const float4*)&b2[c0];
#pragma unroll
    for (int r = 0; r < 4; ++r) {
        int gn = n_base + n0 + r;
        if (gn < N) {
            float d = g_degf[gn];
            float4 v = acc[r];
            v.x = fmaf(d, b2v.x, v.x); v.y = fmaf(d, b2v.y, v.y);
            v.z = fmaf(d, b2v.z, v.z); v.w = fmaf(d, b2v.w, v.w);
            *(float4*)&out[(size_t)gn * 64 + c0] = v;
        }
    }
}

// ---------------------------------------------------------------------------
extern "C" void kernel_launch(void* const* d_in, const int* in_sizes, int n_in,
                              void* d_out, int out_size) {
    const float* x          = (const float*)d_in[0];
    const void*  edge_index = d_in[1];
    const float* edge_attr  = (const float*)d_in[2];
    const float* W1         = (const float*)d_in[3];
    const float* b1         = (const float*)d_in[4];
    const float* gamma      = (const float*)d_in[5];
    const float* beta       = (const float*)d_in[6];
    const float* W2         = (const float*)d_in[7];
    const float* b2         = (const float*)d_in[8];
    float*       out        = (float*)d_out;

    int N = in_sizes[0] / 64;     // 100000
    int E = in_sizes[2] / 32;     // 1600000

    const int SM_PRE  = (64 * 65 + 4 + 64 * 128) * 4;
    const int SM_EDGE = 26112;
    const int SM_NODE = (64 * 65 + 4 + 64 * 64) * 4;
    cudaFuncSetAttribute(precompute_kernel, cudaFuncAttributeMaxDynamicSharedMemorySize, SM_PRE);
    cudaFuncSetAttribute(edge_kernel,       cudaFuncAttributeMaxDynamicSharedMemorySize, SM_EDGE);
    cudaFuncSetAttribute(node_kernel,       cudaFuncAttributeMaxDynamicSharedMemorySize, SM_NODE);

    detect_idx_kernel<<<1, 128>>>(edge_index, N);
    precompute_kernel<<<(N + 63) / 64, NTHREADS, SM_PRE>>>(x, W1, b1, N);
    edge_kernel<<<E / E_TILE, NTHREADS, SM_EDGE>>>(edge_index, edge_attr, W1,
                                                   gamma, beta, E);
    node_kernel<<<(N + 63) / 64, NTHREADS, SM_NODE>>>(W2, b2, out, N);
}